// round 3
// baseline (speedup 1.0000x reference)
#include <cuda_runtime.h>
#include <math.h>

// Problem dims (fixed by reference setup_inputs)
#define BB 64
#define FF 128
#define TT 4096
#define KK 13
#define NN (BB*TT)   // 262144 samples per coefficient

// ---- device scratch (static: no allocation allowed) ----
__device__ float  g_basis[KK][FF];
__device__ float  g_cT[KK * NN];       // cepstra, layout [k][b*T+t]
__device__ float  g_cP[KK * NN];
__device__ double g_sum[2][KK];
__device__ double g_sumsq[2][KK];
__device__ float  g_mean[2][KK];
__device__ float  g_rstd[2][KK];
__device__ double g_mcd_acc;

// ---------------------------------------------------------------------------
// K0: zero accumulators, build orthonormal DCT-II basis on device
// ---------------------------------------------------------------------------
__global__ void k0_init() {
    int i = threadIdx.x;
    if (i < KK) {
        g_sum[0][i] = 0.0; g_sum[1][i] = 0.0;
        g_sumsq[0][i] = 0.0; g_sumsq[1][i] = 0.0;
    }
    if (i == 0) g_mcd_acc = 0.0;
    for (int idx = i; idx < KK * FF; idx += blockDim.x) {
        int k = idx / FF, f = idx % FF;
        float scale = (k == 0) ? sqrtf(1.0f / FF) : sqrtf(2.0f / FF);
        g_basis[k][f] = cospif((f + 0.5f) * (float)k / (float)FF) * scale;
    }
}

// ---------------------------------------------------------------------------
// K1: x -> log1p(|x|) -> 13-pt DCT for both tensors. Writes cepstra [k][n].
// One thread handles 2 adjacent t values (float2 coalesced loads/stores).
// Grid: (TT/512, BB), 256 threads.
// ---------------------------------------------------------------------------
__global__ __launch_bounds__(256) void k1_dct(const float* __restrict__ xt,
                                              const float* __restrict__ xp) {
    __shared__ float sb[KK][FF];
    for (int i = threadIdx.x; i < KK * FF; i += blockDim.x)
        ((float*)sb)[i] = ((const float*)g_basis)[i];
    __syncthreads();

    const int b  = blockIdx.y;
    const int t2 = blockIdx.x * blockDim.x + threadIdx.x;   // float2 index along T
    const float2* pt = (const float2*)(xt + (size_t)b * FF * TT);
    const float2* pp = (const float2*)(xp + (size_t)b * FF * TT);

    float aTx[KK], aTy[KK], aPx[KK], aPy[KK];
#pragma unroll
    for (int k = 0; k < KK; k++) { aTx[k]=0.f; aTy[k]=0.f; aPx[k]=0.f; aPy[k]=0.f; }

#pragma unroll 2
    for (int f = 0; f < FF; f++) {
        float2 vt = pt[f * (TT/2) + t2];
        float2 vp = pp[f * (TT/2) + t2];
        float ltx = __logf(1.0f + fabsf(vt.x));
        float lty = __logf(1.0f + fabsf(vt.y));
        float lpx = __logf(1.0f + fabsf(vp.x));
        float lpy = __logf(1.0f + fabsf(vp.y));
#pragma unroll
        for (int k = 0; k < KK; k++) {
            float w = sb[k][f];
            aTx[k] = fmaf(w, ltx, aTx[k]);
            aTy[k] = fmaf(w, lty, aTy[k]);
            aPx[k] = fmaf(w, lpx, aPx[k]);
            aPy[k] = fmaf(w, lpy, aPy[k]);
        }
    }

    const int n2 = b * (TT/2) + t2;   // float2 index into [k][NN]
#pragma unroll
    for (int k = 0; k < KK; k++) {
        ((float2*)(g_cT + (size_t)k * NN))[n2] = make_float2(aTx[k], aTy[k]);
        ((float2*)(g_cP + (size_t)k * NN))[n2] = make_float2(aPx[k], aPy[k]);
    }
}

// ---------------------------------------------------------------------------
// K2: per-coefficient sum / sumsq for both tensors.
// Grid-stride over NN; warp reduce -> shared accum -> 1 global atomic/block/qty.
// ---------------------------------------------------------------------------
__global__ __launch_bounds__(256) void k2_stats() {
    float s[2][KK], ss[2][KK];
#pragma unroll
    for (int t = 0; t < 2; t++)
#pragma unroll
        for (int k = 0; k < KK; k++) { s[t][k] = 0.f; ss[t][k] = 0.f; }

    for (int n = blockIdx.x * blockDim.x + threadIdx.x; n < NN;
         n += gridDim.x * blockDim.x) {
#pragma unroll
        for (int k = 0; k < KK; k++) {
            float a = g_cT[(size_t)k * NN + n];
            float c = g_cP[(size_t)k * NN + n];
            s[0][k] += a; ss[0][k] = fmaf(a, a, ss[0][k]);
            s[1][k] += c; ss[1][k] = fmaf(c, c, ss[1][k]);
        }
    }

    __shared__ float sh_s[2][KK], sh_ss[2][KK];
    if (threadIdx.x < 2 * KK) {
        ((float*)sh_s)[threadIdx.x] = 0.f;
        ((float*)sh_ss)[threadIdx.x] = 0.f;
    }
    __syncthreads();

#pragma unroll
    for (int t = 0; t < 2; t++)
#pragma unroll
        for (int k = 0; k < KK; k++) {
            float v1 = s[t][k], v2 = ss[t][k];
            for (int o = 16; o > 0; o >>= 1) {
                v1 += __shfl_down_sync(0xffffffffu, v1, o);
                v2 += __shfl_down_sync(0xffffffffu, v2, o);
            }
            if ((threadIdx.x & 31) == 0) {
                atomicAdd(&sh_s[t][k], v1);
                atomicAdd(&sh_ss[t][k], v2);
            }
        }
    __syncthreads();
    if (threadIdx.x < 2 * KK) {
        int t = threadIdx.x / KK, k = threadIdx.x % KK;
        atomicAdd(&g_sum[t][k],   (double)sh_s[t][k]);
        atomicAdd(&g_sumsq[t][k], (double)sh_ss[t][k]);
    }
}

// ---------------------------------------------------------------------------
// K2b: finalize mean / 1/(std+1e-6)   (ddof=1, matches torch/jnp std)
// ---------------------------------------------------------------------------
__global__ void k2b_finalize() {
    int i = threadIdx.x;
    if (i < 2 * KK) {
        int t = i / KK, k = i % KK;
        double s  = g_sum[t][k];
        double mean = s / (double)NN;
        double var  = (g_sumsq[t][k] - s * s / (double)NN) / (double)(NN - 1);
        if (var < 0.0) var = 0.0;
        g_mean[t][k] = (float)mean;
        g_rstd[t][k] = (float)(1.0 / (sqrt(var) + 1e-6));
    }
}

// ---------------------------------------------------------------------------
// K3: mcd sum over all (b,t). d_k = cT'*rT - cP'*rP; mcd = sqrt(2*sum d^2)
// (the 10/ln10 scale and /N are applied in K4)
// ---------------------------------------------------------------------------
__global__ __launch_bounds__(256) void k3_mcd() {
    __shared__ float srT[KK], srP[KK], soff[KK];
    if (threadIdx.x < KK) {
        int k = threadIdx.x;
        float rT = g_rstd[0][k], rP = g_rstd[1][k];
        srT[k] = rT; srP[k] = rP;
        soff[k] = g_mean[0][k] * rT - g_mean[1][k] * rP;
    }
    __syncthreads();

    float acc = 0.f;
    for (int n = blockIdx.x * blockDim.x + threadIdx.x; n < NN;
         n += gridDim.x * blockDim.x) {
        float sum = 0.f;
#pragma unroll
        for (int k = 0; k < KK; k++) {
            float d = g_cT[(size_t)k * NN + n] * srT[k]
                    - g_cP[(size_t)k * NN + n] * srP[k]
                    - soff[k];
            sum = fmaf(d, d, sum);
        }
        acc += sqrtf(2.0f * sum);
    }

    __shared__ float sh_acc;
    if (threadIdx.x == 0) sh_acc = 0.f;
    __syncthreads();
    for (int o = 16; o > 0; o >>= 1) acc += __shfl_down_sync(0xffffffffu, acc, o);
    if ((threadIdx.x & 31) == 0) atomicAdd(&sh_acc, acc);
    __syncthreads();
    if (threadIdx.x == 0) atomicAdd(&g_mcd_acc, (double)sh_acc);
}

// ---------------------------------------------------------------------------
// K4: final scalar
// ---------------------------------------------------------------------------
__global__ void k4_final(float* out) {
    // 10 / ln(10)
    out[0] = (float)(g_mcd_acc * 4.342944819032518 / (double)NN);
}

extern "C" void kernel_launch(void* const* d_in, const int* in_sizes, int n_in,
                              void* d_out, int out_size) {
    const float* mel_true = (const float*)d_in[0];
    const float* mel_pred = (const float*)d_in[1];
    float* out = (float*)d_out;

    k0_init<<<1, 256>>>();

    dim3 g1(TT / 512, BB);           // 8 x 64 = 512 blocks, 2 t per thread
    k1_dct<<<g1, 256>>>(mel_true, mel_pred);

    k2_stats<<<512, 256>>>();
    k2b_finalize<<<1, 32>>>();
    k3_mcd<<<512, 256>>>();
    k4_final<<<1, 1>>>(out);
}